// round 2
// baseline (speedup 1.0000x reference)
#include <cuda_runtime.h>
#include <cstdint>

#define DD 1024
#define HH 1024
#define NB 8
#define NS 40
#define NL 20
#define MI 320        // B*N rows of f
#define MJ 160        // B*L rows of v
#define MG 51200      // MI*MJ grounding pairs
#define NPAIR 780     // triu_indices(40, k=1)
#define MT 6240       // B*NPAIR text rows
#define K3 3072

// Scratch (static device globals; no runtime allocation anywhere)
__device__ float g_Apre[MI * HH];            // f @ Wf
__device__ float g_Cpre[MJ * HH];            // v @ Ws
__device__ float g_H1[(size_t)MG * HH];      // grounding hidden (210 MB)
__device__ float g_Xt[(size_t)MT * K3];      // text concat input (77 MB)
__device__ float g_Ht[(size_t)MT * HH];      // text hidden (26 MB)

// ---------------------------------------------------------------------------
// Generic SGEMM: C = act(A[MxK] @ B[KxN] + bias), row-major, N multiple of 64,
// K multiple of 16. 64x64 block tile, 256 threads, 4x4 per thread.
// Output / optional input selected device-side from the scratch globals so the
// host never needs cudaGetSymbolAddress.
//   a_sel: 0 -> use Aext, 1 -> g_Xt
//   c_sel: 0 -> g_Apre, 1 -> g_Cpre, 2 -> g_Ht
// ---------------------------------------------------------------------------
__global__ __launch_bounds__(256) void sgemm_kernel(
    const float* __restrict__ Aext, int a_sel, const float* __restrict__ Bm,
    const float* __restrict__ bias, int c_sel,
    int M, int N, int K, int do_relu)
{
    const float* A = (a_sel == 0) ? Aext : g_Xt;
    float* C = (c_sel == 0) ? g_Apre : (c_sel == 1) ? g_Cpre : g_Ht;

    __shared__ __align__(16) float As[16][66];
    __shared__ __align__(16) float Bs[16][64];
    int tid = threadIdx.x;
    int tx = tid & 15, ty = tid >> 4;
    int row0 = blockIdx.y * 64, col0 = blockIdx.x * 64;
    float acc[4][4] = {};
    for (int kt = 0; kt < K; kt += 16) {
        #pragma unroll
        for (int l = 0; l < 4; l++) {
            int idx = tid + l * 256;
            int m = idx >> 4, kk = idx & 15;
            int gr = row0 + m;
            As[kk][m] = (gr < M) ? A[(size_t)gr * K + kt + kk] : 0.f;
        }
        #pragma unroll
        for (int l = 0; l < 4; l++) {
            int idx = tid + l * 256;
            int kk = idx >> 6, c = idx & 63;
            Bs[kk][c] = Bm[(size_t)(kt + kk) * N + col0 + c];
        }
        __syncthreads();
        #pragma unroll
        for (int kk = 0; kk < 16; kk++) {
            float av[4], bv[4];
            #pragma unroll
            for (int i = 0; i < 4; i++) av[i] = As[kk][ty * 4 + i];
            float4 b4 = *(const float4*)&Bs[kk][tx * 4];
            bv[0] = b4.x; bv[1] = b4.y; bv[2] = b4.z; bv[3] = b4.w;
            #pragma unroll
            for (int i = 0; i < 4; i++)
                #pragma unroll
                for (int j = 0; j < 4; j++)
                    acc[i][j] += av[i] * bv[j];
        }
        __syncthreads();
    }
    #pragma unroll
    for (int i = 0; i < 4; i++) {
        int r = row0 + ty * 4 + i;
        if (r >= M) continue;
        #pragma unroll
        for (int j = 0; j < 4; j++) {
            int c = col0 + tx * 4 + j;
            float vl = acc[i][j];
            if (bias) vl += bias[c];
            if (do_relu) vl = fmaxf(vl, 0.f);
            C[(size_t)r * N + c] = vl;
        }
    }
}

// ---------------------------------------------------------------------------
// Grounding layer 1: H1[r,c] = relu((f_i ⊙ v_j) @ Wp + Apre[i,c] + Cpre[j,c] + b1[c])
// r = i*160 + j; M = 51200, N = K = 1024. A-tile generated on the fly.
// ---------------------------------------------------------------------------
__global__ __launch_bounds__(256) void ground_h1_kernel(
    const float* __restrict__ f, const float* __restrict__ v,
    const float* __restrict__ Wp, const float* __restrict__ b1)
{
    __shared__ __align__(16) float As[16][66];
    __shared__ __align__(16) float Bs[16][64];
    int tid = threadIdx.x;
    int tx = tid & 15, ty = tid >> 4;
    int row0 = blockIdx.y * 64, col0 = blockIdx.x * 64;
    float acc[4][4] = {};
    for (int kt = 0; kt < DD; kt += 16) {
        #pragma unroll
        for (int l = 0; l < 4; l++) {
            int idx = tid + l * 256;
            int m = idx >> 4, kk = idx & 15;
            int gr = row0 + m;
            int gi = gr / MJ, gj = gr - gi * MJ;
            As[kk][m] = f[(size_t)gi * DD + kt + kk] * v[(size_t)gj * DD + kt + kk];
        }
        #pragma unroll
        for (int l = 0; l < 4; l++) {
            int idx = tid + l * 256;
            int kk = idx >> 6, c = idx & 63;
            Bs[kk][c] = Wp[(size_t)(kt + kk) * HH + col0 + c];
        }
        __syncthreads();
        #pragma unroll
        for (int kk = 0; kk < 16; kk++) {
            float av[4], bv[4];
            #pragma unroll
            for (int i = 0; i < 4; i++) av[i] = As[kk][ty * 4 + i];
            float4 b4 = *(const float4*)&Bs[kk][tx * 4];
            bv[0] = b4.x; bv[1] = b4.y; bv[2] = b4.z; bv[3] = b4.w;
            #pragma unroll
            for (int i = 0; i < 4; i++)
                #pragma unroll
                for (int j = 0; j < 4; j++)
                    acc[i][j] += av[i] * bv[j];
        }
        __syncthreads();
    }
    #pragma unroll
    for (int i = 0; i < 4; i++) {
        int r = row0 + ty * 4 + i;
        int gi = r / MJ, gj = r - gi * MJ;
        #pragma unroll
        for (int j = 0; j < 4; j++) {
            int c = col0 + tx * 4 + j;
            float vl = acc[i][j] + g_Apre[(size_t)gi * HH + c] + g_Cpre[(size_t)gj * HH + c] + b1[c];
            g_H1[(size_t)r * HH + c] = fmaxf(vl, 0.f);
        }
    }
}

// ---------------------------------------------------------------------------
// Fused tail: out[r] = relu(H[r,:] @ W2 + b2) @ W3 + b3  (optionally * mask)
// h_sel: 0 -> g_H1, 1 -> g_Ht. Deterministic block reduction, no atomics.
// ---------------------------------------------------------------------------
__global__ __launch_bounds__(256) void tail_fused_kernel(
    int h_sel, const float* __restrict__ W2,
    const float* __restrict__ b2, const float* __restrict__ W3,
    const float* __restrict__ b3v, const float* __restrict__ sm,
    const float* __restrict__ im, float* __restrict__ outp,
    int M, int masked)
{
    const float* Hm = (h_sel == 0) ? g_H1 : g_Ht;
    __shared__ __align__(16) float As[16][66];
    __shared__ __align__(16) float Bs[16][64];
    __shared__ float red[64 * 16];
    int tid = threadIdx.x;
    int tx = tid & 15, ty = tid >> 4;
    int row0 = blockIdx.x * 64;
    float rsum[4] = {0.f, 0.f, 0.f, 0.f};
    for (int nc = 0; nc < HH; nc += 64) {
        float acc[4][4] = {};
        for (int kt = 0; kt < HH; kt += 16) {
            #pragma unroll
            for (int l = 0; l < 4; l++) {
                int idx = tid + l * 256;
                int m = idx >> 4, kk = idx & 15;
                int gr = row0 + m;
                As[kk][m] = (gr < M) ? Hm[(size_t)gr * HH + kt + kk] : 0.f;
            }
            #pragma unroll
            for (int l = 0; l < 4; l++) {
                int idx = tid + l * 256;
                int kk = idx >> 6, c = idx & 63;
                Bs[kk][c] = W2[(size_t)(kt + kk) * HH + nc + c];
            }
            __syncthreads();
            #pragma unroll
            for (int kk = 0; kk < 16; kk++) {
                float av[4], bv[4];
                #pragma unroll
                for (int i = 0; i < 4; i++) av[i] = As[kk][ty * 4 + i];
                float4 b4 = *(const float4*)&Bs[kk][tx * 4];
                bv[0] = b4.x; bv[1] = b4.y; bv[2] = b4.z; bv[3] = b4.w;
                #pragma unroll
                for (int i = 0; i < 4; i++)
                    #pragma unroll
                    for (int j = 0; j < 4; j++)
                        acc[i][j] += av[i] * bv[j];
            }
            __syncthreads();
        }
        #pragma unroll
        for (int j = 0; j < 4; j++) {
            int c = nc + tx * 4 + j;
            float w3 = W3[c], bb = b2[c];
            #pragma unroll
            for (int i = 0; i < 4; i++)
                rsum[i] += fmaxf(acc[i][j] + bb, 0.f) * w3;
        }
    }
    #pragma unroll
    for (int i = 0; i < 4; i++) red[(ty * 4 + i) * 16 + tx] = rsum[i];
    __syncthreads();
    if (tid < 64) {
        int r = row0 + tid;
        if (r < M) {
            float s = 0.f;
            #pragma unroll
            for (int t = 0; t < 16; t++) s += red[tid * 16 + t];
            s += b3v[0];
            if (masked) {
                int gi = r / MJ, gj = r - gi * MJ;
                s *= sm[gi] * im[gj];
            }
            outp[r] = s;
        }
    }
}

// ---------------------------------------------------------------------------
// Build text concat input: Xt[b*780+p] = [span[b,fi], span[b,si], span[b,fi]*span[b,si]]
// ---------------------------------------------------------------------------
__global__ void build_xt_kernel(const float* __restrict__ span)
{
    int r = blockIdx.x;
    int b = r / NPAIR, p = r - b * NPAIR;
    int n = 0, rem = p;
    while (rem >= (NS - 1 - n)) { rem -= (NS - 1 - n); n++; }
    int fi = n, si = n + 1 + rem;
    const float* a = span + ((size_t)b * NS + fi) * DD;
    const float* c = span + ((size_t)b * NS + si) * DD;
    float* x = g_Xt + (size_t)r * K3;
    for (int d = threadIdx.x; d < DD; d += blockDim.x) {
        float av = a[d], cv = c[d];
        x[d] = av;
        x[DD + d] = cv;
        x[2 * DD + d] = av * cv;
    }
}

// ---------------------------------------------------------------------------
// S[8][8] = chunk sums of 800 grounding scores; loss = bidirectional NCE.
// ---------------------------------------------------------------------------
__global__ void loss_kernel(const float* __restrict__ gsc, float* __restrict__ out0)
{
    __shared__ float S[64];
    __shared__ float red[256];
    int tid = threadIdx.x;
    int e = tid >> 2, q = tid & 3;
    float s = 0.f;
    const float* base = gsc + e * 800;
    for (int k = q; k < 800; k += 4) s += base[k];
    red[tid] = s;
    __syncthreads();
    if (q == 0) S[e] = red[tid] + red[tid + 1] + red[tid + 2] + red[tid + 3];
    __syncthreads();
    if (tid == 0) {
        float loss = 0.f;
        for (int a = 0; a < 8; a++) {
            float mx = -1e30f;
            for (int b = 0; b < 8; b++) mx = fmaxf(mx, S[a * 8 + b]);
            float se = 0.f;
            for (int b = 0; b < 8; b++) se += expf(S[a * 8 + b] - mx);
            float lse = mx + logf(se);
            for (int b = 0; b < 8; b++) loss -= (S[a * 8 + b] - lse);
        }
        for (int b = 0; b < 8; b++) {
            float mx = -1e30f;
            for (int a = 0; a < 8; a++) mx = fmaxf(mx, S[a * 8 + b]);
            float se = 0.f;
            for (int a = 0; a < 8; a++) se += expf(S[a * 8 + b] - mx);
            float lse = mx + logf(se);
            for (int a = 0; a < 8; a++) loss -= (S[a * 8 + b] - lse);
        }
        out0[0] = loss / 8.0f;
    }
}

extern "C" void kernel_launch(void* const* d_in, const int* in_sizes, int n_in,
                              void* d_out, int out_size)
{
    const float* span  = (const float*)d_in[0];
    const float* img   = (const float*)d_in[1];
    const float* smask = (const float*)d_in[2];
    const float* imask = (const float*)d_in[3];
    const float* tW1 = (const float*)d_in[4];
    const float* tb1 = (const float*)d_in[5];
    const float* tW2 = (const float*)d_in[6];
    const float* tb2 = (const float*)d_in[7];
    const float* tW3 = (const float*)d_in[8];
    const float* tb3 = (const float*)d_in[9];
    const float* gW1 = (const float*)d_in[10];
    const float* gb1 = (const float*)d_in[11];
    const float* gW2 = (const float*)d_in[12];
    const float* gb2 = (const float*)d_in[13];
    const float* gW3 = (const float*)d_in[14];
    const float* gb3 = (const float*)d_in[15];
    float* out = (float*)d_out;

    dim3 blk(256);

    // Grounding path
    sgemm_kernel<<<dim3(16, 5), blk>>>(span, 0, gW1, nullptr, 0, MI, HH, DD, 0);
    sgemm_kernel<<<dim3(16, 3), blk>>>(img, 0, gW1 + (size_t)DD * HH, nullptr, 1, MJ, HH, DD, 0);
    ground_h1_kernel<<<dim3(16, MG / 64), blk>>>(span, img, gW1 + (size_t)2 * DD * HH, gb1);
    tail_fused_kernel<<<dim3(MG / 64), blk>>>(0, gW2, gb2, gW3, gb3,
                                              smask, imask, out + 1, MG, 1);

    // Text path
    build_xt_kernel<<<dim3(MT), blk>>>(span);
    sgemm_kernel<<<dim3(16, (MT + 63) / 64), blk>>>(nullptr, 1, tW1, tb1, 2, MT, HH, K3, 1);
    tail_fused_kernel<<<dim3((MT + 63) / 64), blk>>>(1, tW2, tb2, tW3, tb3,
                                                     nullptr, nullptr, out + 1 + MG, MT, 0);

    // S and loss (reads masked grounding scores from out)
    loss_kernel<<<1, 256>>>(out + 1, out);
}